// round 12
// baseline (speedup 1.0000x reference)
#include <cuda_runtime.h>
#include <cstdint>
#include <math.h>

#define BB 8
#define CC 256
#define NN 4096        // 64*64
#define WH 64
#define MMK 23
#define PADK 11
#define OCH 144        // 64 q + 16 k + 64 v

// ---- scratch (static device globals; no allocation anywhere) ----
__device__ float g_Wf[OCH * CC];          // BN-folded weights
__device__ float g_bf[OCH];               // folded bias
__device__ float g_q [BB * 64 * NN];      // q after BN
__device__ float g_kf[BB * 16 * NN];      // k pre-softmax
__device__ float g_v [BB * 64 * NN];      // v after BN
__device__ float g_lc[BB * 16 * 64];      // content lambda

// ============ K0: fold BN into weights ============
__global__ void fold_kernel(const float* __restrict__ Wq,
                            const float* __restrict__ qg, const float* __restrict__ qb,
                            const float* __restrict__ qm, const float* __restrict__ qv,
                            const float* __restrict__ Wk, const float* __restrict__ Wv,
                            const float* __restrict__ vg, const float* __restrict__ vb,
                            const float* __restrict__ vm, const float* __restrict__ vvar)
{
    int o = blockIdx.x;
    int c = threadIdx.x;
    float w, bias = 0.f;
    if (o < 64) {
        float s = qg[o] * rsqrtf(qv[o] + 1e-5f);
        w = Wq[o * CC + c] * s;
        bias = qb[o] - qm[o] * s;
    } else if (o < 80) {
        int oo = o - 64;
        w = Wk[oo * CC + c];
    } else {
        int oo = o - 80;
        float s = vg[oo] * rsqrtf(vvar[oo] + 1e-5f);
        w = Wv[oo * CC + c] * s;
        bias = vb[oo] - vm[oo] * s;
    }
    g_Wf[o * CC + c] = w;
    if (c == 0) g_bf[o] = bias;
}

// ============ K1: fused projection GEMM (144 x 4096, K=256) per batch ============
__global__ void __launch_bounds__(256) proj_kernel(const float* __restrict__ x)
{
    __shared__ float xs[32][132];
    __shared__ float ws[OCH][33];
    int b = blockIdx.y;
    int n0 = blockIdx.x * 128;
    int t = threadIdx.x;
    int tx = t & 15, ty = t >> 4;

    float acc[9][8];
#pragma unroll
    for (int r = 0; r < 9; r++)
#pragma unroll
        for (int j = 0; j < 8; j++) acc[r][j] = 0.f;

    for (int kc = 0; kc < CC; kc += 32) {
        for (int i = t; i < OCH * 32; i += 256) {
            int o = i >> 5, c = i & 31;
            ws[o][c] = g_Wf[o * CC + kc + c];
        }
        for (int i = t; i < 32 * 128; i += 256) {
            int c = i >> 7, n = i & 127;
            xs[c][n] = x[((size_t)b * CC + kc + c) * NN + n0 + n];
        }
        __syncthreads();
#pragma unroll 8
        for (int kk = 0; kk < 32; kk++) {
            float xv[8];
#pragma unroll
            for (int j = 0; j < 8; j++) xv[j] = xs[kk][tx * 8 + j];
#pragma unroll
            for (int r = 0; r < 9; r++) {
                float a = ws[ty + 16 * r][kk];
#pragma unroll
                for (int j = 0; j < 8; j++) acc[r][j] += a * xv[j];
            }
        }
        __syncthreads();
    }

#pragma unroll
    for (int r = 0; r < 9; r++) {
        int o = ty + 16 * r;
        float bias = g_bf[o];
        float* dst;
        if (o < 64)       dst = &g_q [((size_t)b * 64 + o)        * NN];
        else if (o < 80)  dst = &g_kf[((size_t)b * 16 + (o - 64)) * NN];
        else              dst = &g_v [((size_t)b * 64 + (o - 80)) * NN];
#pragma unroll
        for (int j = 0; j < 8; j++) dst[n0 + tx * 8 + j] = acc[r][j] + bias;
    }
}

// ============ K2: softmax + lambda_c, register-resident (grid 128 = b*16+k) ====
// softmax vals stay in regs; lc[b,k,v] = sum_n softmax(kf)[n] * v[b,v,n]
// via per-warp shuffle reduction. No kf writeback, no atomics, no zeroing.
__global__ void __launch_bounds__(256) softmax_lc_kernel()
{
    __shared__ float red[256];
    __shared__ float part[8][64];

    const int row = blockIdx.x;           // b*16 + k
    const int b = row >> 4, k = row & 15;
    const int t = threadIdx.x;
    const int l = t & 31, w = t >> 5;

    const float* p = &g_kf[(size_t)row * NN];
    float vals[16];
    float m = -1e30f;
#pragma unroll
    for (int i = 0; i < 16; i++) {
        vals[i] = p[t + 256 * i];
        m = fmaxf(m, vals[i]);
    }
    red[t] = m; __syncthreads();
    for (int s = 128; s > 0; s >>= 1) {
        if (t < s) red[t] = fmaxf(red[t], red[t + s]);
        __syncthreads();
    }
    m = red[0]; __syncthreads();

    float sum = 0.f;
#pragma unroll
    for (int i = 0; i < 16; i++) {
        vals[i] = __expf(vals[i] - m);
        sum += vals[i];
    }
    red[t] = sum; __syncthreads();
    for (int s = 128; s > 0; s >>= 1) {
        if (t < s) red[t] += red[t + s];
        __syncthreads();
    }
    const float inv = 1.f / red[0];
#pragma unroll
    for (int i = 0; i < 16; i++) vals[i] *= inv;

    const float* vb = &g_v[(size_t)b * 64 * NN];
#pragma unroll 1
    for (int v = 0; v < 64; v += 4) {
        float s0 = 0.f, s1 = 0.f, s2 = 0.f, s3 = 0.f;
#pragma unroll
        for (int i = 0; i < 16; i++) {
            int n = t + 256 * i;
            s0 += vals[i] * vb[(size_t)(v + 0) * NN + n];
            s1 += vals[i] * vb[(size_t)(v + 1) * NN + n];
            s2 += vals[i] * vb[(size_t)(v + 2) * NN + n];
            s3 += vals[i] * vb[(size_t)(v + 3) * NN + n];
        }
#pragma unroll
        for (int off = 16; off > 0; off >>= 1) {
            s0 += __shfl_down_sync(0xffffffffu, s0, off);
            s1 += __shfl_down_sync(0xffffffffu, s1, off);
            s2 += __shfl_down_sync(0xffffffffu, s2, off);
            s3 += __shfl_down_sync(0xffffffffu, s3, off);
        }
        if (l == 0) {
            part[w][v + 0] = s0; part[w][v + 1] = s1;
            part[w][v + 2] = s2; part[w][v + 3] = s3;
        }
    }
    __syncthreads();
    if (t < 64) {
        float s = 0.f;
#pragma unroll
        for (int ww = 0; ww < 8; ww++) s += part[ww][t];
        g_lc[b * 1024 + k * 64 + t] = s;
    }
}

// ============ K3: fused positional lambda + output (v4 scalar, proven) ========
// out[b, h*64+v, (r,c)] = sum_k q[h,k,(r,c)] * lc[k,v]
//                       + sum_{di,dj} s[h,(di,dj),(r,c)] * v[v, r+di-11, c+dj-11]
// where s[h,(di,dj),(r,c)] = sum_k q[h,k,(r,c)] * emb[k,di,dj]
#define FUSED_SMEM_BYTES 100416

__global__ void __launch_bounds__(256, 2) fused_kernel(const float* __restrict__ emb,
                                                       float* __restrict__ out)
{
    extern __shared__ float sm[];
    float* q_s   = sm;            // [64 ch][64 c]
    float* lc_s  = sm + 4096;     // [16][64]
    float* emb_t = sm + 5120;     // [529 p][16 k]  (transposed)
    float* s_s   = sm + 13584;    // [4h][23dj][64c]
    float* vr_s  = sm + 19472;    // [64v][88]

    const int r = blockIdx.x, b = blockIdx.y;
    const int t = threadIdx.x;
    const int w = t >> 5, l = t & 31;

    // apply mapping: warp covers 8 strips x 4 vgroups (1-wf sh broadcasts)
    const int strip  = (l & 7) | ((w & 1) << 3);
    const int vgroup = (l >> 3) | ((w >> 1) << 2);
    const int c0 = strip * 4, v0 = vgroup * 4;

    // s-compute mapping: hh constant per warp, 6 dj per thread
    const int hh  = w & 3;
    const int djb = ((w >> 2) * 12) + ((l >> 4) * 6);   // 0,6,12,18
    const int cq  = l & 15;

    // v-row fill mapping
    const int col = t & 63, vv0 = t >> 6;

    // ---- persistent tiles ----
    for (int i = t; i < 4096; i += 256) {
        int ch = i >> 6, c = i & 63;
        q_s[i] = g_q[((size_t)b * 64 + ch) * NN + r * WH + c];
    }
    for (int i = t; i < 1024; i += 256) lc_s[i] = g_lc[b * 1024 + i];
    for (int i = t; i < 8464; i += 256) {
        int p = i >> 4, k = i & 15;               // transpose on load
        emb_t[i] = emb[k * 529 + p];
    }
    for (int i = t; i < 5632; i += 256) vr_s[i] = 0.f;   // halo stays zero
    __syncthreads();

    // ---- init acc with content lambda ----
    float acc[4][4][4];
#pragma unroll
    for (int h = 0; h < 4; h++)
#pragma unroll
        for (int v = 0; v < 4; v++)
#pragma unroll
            for (int c = 0; c < 4; c++) acc[h][v][c] = 0.f;

    const float4* q4 = (const float4*)q_s;          // [64 ch][16] float4
#pragma unroll
    for (int k = 0; k < 16; k++) {
        float lv[4];
#pragma unroll
        for (int v = 0; v < 4; v++) lv[v] = lc_s[k * 64 + v0 + v];
#pragma unroll
        for (int h = 0; h < 4; h++) {
            float4 qv = q4[(h * 16 + k) * 16 + strip];
#pragma unroll
            for (int v = 0; v < 4; v++) {
                acc[h][v][0] += qv.x * lv[v]; acc[h][v][1] += qv.y * lv[v];
                acc[h][v][2] += qv.z * lv[v]; acc[h][v][3] += qv.w * lv[v];
            }
        }
    }

    const int di_lo = (r < PADK) ? (PADK - r) : 0;
    const int di_hi = (r > 52) ? (74 - r) : 22;
    const float* vbase = &g_v[(size_t)b * 64 * NN];
    float4* s4 = (float4*)s_s;                      // [4*23][16] float4

#pragma unroll 1
    for (int di = di_lo; di <= di_hi; di++) {
        const int rr = r + di - PADK;
        __syncthreads();   // A: previous apply done reading s_s / vr_s

        // prefetch v row (global, latency hidden behind s-compute)
        float vreg[16];
#pragma unroll
        for (int i = 0; i < 16; i++)
            vreg[i] = vbase[(size_t)(4 * i + vv0) * NN + rr * WH + col];

        // ---- s-compute: (hh, cq), dj in [djb, djb+5]; sv accumulators ----
        {
            float4 sv[6];
#pragma unroll
            for (int j = 0; j < 6; j++) sv[j] = make_float4(0.f, 0.f, 0.f, 0.f);

            const float* ebase = &emb_t[(di * MMK) * 16];
#pragma unroll
            for (int kc = 0; kc < 4; kc++) {
                float4 qr[4];
#pragma unroll
                for (int kk = 0; kk < 4; kk++)
                    qr[kk] = q4[(hh * 16 + kc * 4 + kk) * 16 + cq];
#pragma unroll
                for (int j = 0; j < 6; j++) {
                    const int dj = djb + j;
                    if (dj < MMK) {
                        float4 ew = *(const float4*)&ebase[dj * 16 + kc * 4];
                        sv[j].x += ew.x * qr[0].x + ew.y * qr[1].x
                                 + ew.z * qr[2].x + ew.w * qr[3].x;
                        sv[j].y += ew.x * qr[0].y + ew.y * qr[1].y
                                 + ew.z * qr[2].y + ew.w * qr[3].y;
                        sv[j].z += ew.x * qr[0].z + ew.y * qr[1].z
                                 + ew.z * qr[2].z + ew.w * qr[3].z;
                        sv[j].w += ew.x * qr[0].w + ew.y * qr[1].w
                                 + ew.z * qr[2].w + ew.w * qr[3].w;
                    }
                }
            }
#pragma unroll
            for (int j = 0; j < 6; j++) {
                const int dj = djb + j;
                if (dj < MMK) s4[(hh * 23 + dj) * 16 + cq] = sv[j];
            }
        }

        // store prefetched v row
#pragma unroll
        for (int i = 0; i < 16; i++)
            vr_s[(4 * i + vv0) * 88 + PADK + col] = vreg[i];
        __syncthreads();   // B: s_s and vr_s ready

        // ---- apply: sliding 8-float window per v channel ----
        float vw[4][8];
#pragma unroll
        for (int v = 0; v < 4; v++) {
            float4 a0 = *(const float4*)&vr_s[(v0 + v) * 88 + c0];
            float4 a1 = *(const float4*)&vr_s[(v0 + v) * 88 + c0 + 4];
            vw[v][0] = a0.x; vw[v][1] = a0.y; vw[v][2] = a0.z; vw[v][3] = a0.w;
            vw[v][4] = a1.x; vw[v][5] = a1.y; vw[v][6] = a1.z; vw[v][7] = a1.w;
        }

#pragma unroll
        for (int djq = 0; djq < 6; djq++) {
#pragma unroll
            for (int djl = 0; djl < 4; djl++) {
                const int dj = djq * 4 + djl;
                if (dj < MMK) {
                    float4 sh[4];
#pragma unroll
                    for (int h = 0; h < 4; h++)
                        sh[h] = s4[(h * 23 + dj) * 16 + strip];
#pragma unroll
                    for (int h = 0; h < 4; h++)
#pragma unroll
                        for (int v = 0; v < 4; v++) {
                            acc[h][v][0] += sh[h].x * vw[v][djl + 0];
                            acc[h][v][1] += sh[h].y * vw[v][djl + 1];
                            acc[h][v][2] += sh[h].z * vw[v][djl + 2];
                            acc[h][v][3] += sh[h].w * vw[v][djl + 3];
                        }
                }
            }
            if (djq < 5) {
#pragma unroll
                for (int v = 0; v < 4; v++) {
                    vw[v][0] = vw[v][4]; vw[v][1] = vw[v][5];
                    vw[v][2] = vw[v][6]; vw[v][3] = vw[v][7];
                    float4 nx = *(const float4*)&vr_s[(v0 + v) * 88 + c0 + (djq + 2) * 4];
                    vw[v][4] = nx.x; vw[v][5] = nx.y; vw[v][6] = nx.z; vw[v][7] = nx.w;
                }
            }
        }
    }

    // ---- output ----
#pragma unroll
    for (int h = 0; h < 4; h++)
#pragma unroll
        for (int v = 0; v < 4; v++) {
            float4 o4 = make_float4(acc[h][v][0], acc[h][v][1],
                                    acc[h][v][2], acc[h][v][3]);
            *(float4*)&out[((size_t)b * 256 + h * 64 + v0 + v) * NN + r * WH + c0] = o4;
        }
}

// ============ launcher ============
extern "C" void kernel_launch(void* const* d_in, const int* in_sizes, int n_in,
                              void* d_out, int out_size)
{
    const float* x   = (const float*)d_in[0];
    const float* Wq  = (const float*)d_in[1];
    const float* qg  = (const float*)d_in[2];
    const float* qb  = (const float*)d_in[3];
    const float* qm  = (const float*)d_in[4];
    const float* qv  = (const float*)d_in[5];
    const float* Wk  = (const float*)d_in[6];
    const float* Wv  = (const float*)d_in[7];
    const float* vg  = (const float*)d_in[8];
    const float* vb  = (const float*)d_in[9];
    const float* vm  = (const float*)d_in[10];
    const float* vvr = (const float*)d_in[11];
    const float* emb = (const float*)d_in[12];
    float* out = (float*)d_out;

    cudaFuncSetAttribute(fused_kernel,
                         cudaFuncAttributeMaxDynamicSharedMemorySize,
                         FUSED_SMEM_BYTES);

    fold_kernel<<<OCH, 256>>>(Wq, qg, qb, qm, qv, Wk, Wv, vg, vb, vm, vvr);
    proj_kernel<<<dim3(32, BB), 256>>>(x);
    softmax_lc_kernel<<<BB * 16, 256>>>();
    fused_kernel<<<dim3(WH, BB), 256, FUSED_SMEM_BYTES>>>(emb, out);
}

// round 13
// speedup vs baseline: 1.2021x; 1.2021x over previous
#include <cuda_runtime.h>
#include <cstdint>
#include <math.h>

#define BB 8
#define CC 256
#define NN 4096        // 64*64
#define WH 64
#define MMK 23
#define PADK 11
#define OCH 144        // 64 q + 16 k + 64 v

// ---- scratch (static device globals; no allocation anywhere) ----
__device__ float g_Wf[OCH * CC];          // BN-folded weights
__device__ float g_bf[OCH];               // folded bias
__device__ float g_q [BB * 64 * NN];      // q after BN
__device__ float g_kf[BB * 16 * NN];      // k, softmaxed in place
__device__ float g_v [BB * 64 * NN];      // v after BN
__device__ float g_lc[BB * 16 * 64];      // content lambda

// ============ K0: fold BN into weights ============
__global__ void fold_kernel(const float* __restrict__ Wq,
                            const float* __restrict__ qg, const float* __restrict__ qb,
                            const float* __restrict__ qm, const float* __restrict__ qv,
                            const float* __restrict__ Wk, const float* __restrict__ Wv,
                            const float* __restrict__ vg, const float* __restrict__ vb,
                            const float* __restrict__ vm, const float* __restrict__ vvar)
{
    int o = blockIdx.x;
    int c = threadIdx.x;
    float w, bias = 0.f;
    if (o < 64) {
        float s = qg[o] * rsqrtf(qv[o] + 1e-5f);
        w = Wq[o * CC + c] * s;
        bias = qb[o] - qm[o] * s;
    } else if (o < 80) {
        int oo = o - 64;
        w = Wk[oo * CC + c];
    } else {
        int oo = o - 80;
        float s = vg[oo] * rsqrtf(vvar[oo] + 1e-5f);
        w = Wv[oo * CC + c] * s;
        bias = vb[oo] - vm[oo] * s;
    }
    g_Wf[o * CC + c] = w;
    if (c == 0) g_bf[o] = bias;
}

// ============ K1: zero lambda_c (graph replays -> must re-zero) ============
__global__ void zero_lc_kernel()
{
    int i = blockIdx.x * 256 + threadIdx.x;
    if (i < BB * 16 * 64) g_lc[i] = 0.f;
}

// ============ K2: fused projection GEMM (144 x 4096, K=256) per batch ============
__global__ void __launch_bounds__(256) proj_kernel(const float* __restrict__ x)
{
    __shared__ float xs[32][132];
    __shared__ float ws[OCH][33];
    int b = blockIdx.y;
    int n0 = blockIdx.x * 128;
    int t = threadIdx.x;
    int tx = t & 15, ty = t >> 4;

    float acc[9][8];
#pragma unroll
    for (int r = 0; r < 9; r++)
#pragma unroll
        for (int j = 0; j < 8; j++) acc[r][j] = 0.f;

    for (int kc = 0; kc < CC; kc += 32) {
        for (int i = t; i < OCH * 32; i += 256) {
            int o = i >> 5, c = i & 31;
            ws[o][c] = g_Wf[o * CC + kc + c];
        }
        // x tile: float4 loads (32 rows x 128 cols = 1024 float4)
        for (int i = t; i < 32 * 32; i += 256) {
            int c = i >> 5, n4 = i & 31;
            float4 xv4 = *(const float4*)&x[((size_t)b * CC + kc + c) * NN + n0 + n4 * 4];
            xs[c][n4 * 4 + 0] = xv4.x; xs[c][n4 * 4 + 1] = xv4.y;
            xs[c][n4 * 4 + 2] = xv4.z; xs[c][n4 * 4 + 3] = xv4.w;
        }
        __syncthreads();
#pragma unroll 8
        for (int kk = 0; kk < 32; kk++) {
            float xv[8];
#pragma unroll
            for (int j = 0; j < 8; j++) xv[j] = xs[kk][tx * 8 + j];
#pragma unroll
            for (int r = 0; r < 9; r++) {
                float a = ws[ty + 16 * r][kk];
#pragma unroll
                for (int j = 0; j < 8; j++) acc[r][j] += a * xv[j];
            }
        }
        __syncthreads();
    }

#pragma unroll
    for (int r = 0; r < 9; r++) {
        int o = ty + 16 * r;
        float bias = g_bf[o];
        float* dst;
        if (o < 64)       dst = &g_q [((size_t)b * 64 + o)        * NN];
        else if (o < 80)  dst = &g_kf[((size_t)b * 16 + (o - 64)) * NN];
        else              dst = &g_v [((size_t)b * 64 + (o - 80)) * NN];
        float4 o0 = make_float4(acc[r][0] + bias, acc[r][1] + bias,
                                acc[r][2] + bias, acc[r][3] + bias);
        float4 o1 = make_float4(acc[r][4] + bias, acc[r][5] + bias,
                                acc[r][6] + bias, acc[r][7] + bias);
        *(float4*)&dst[n0 + tx * 8]     = o0;
        *(float4*)&dst[n0 + tx * 8 + 4] = o1;
    }
}

// ============ K3: softmax over n for each (b,k) row ============
__global__ void softmax_kernel()
{
    int row = blockIdx.x;                 // b*16 + k
    float* p = &g_kf[(size_t)row * NN];
    int t = threadIdx.x;
    __shared__ float red[256];

    float vals[16];
    float m = -1e30f;
#pragma unroll
    for (int i = 0; i < 16; i++) {
        vals[i] = p[t + 256 * i];
        m = fmaxf(m, vals[i]);
    }
    red[t] = m; __syncthreads();
    for (int s = 128; s > 0; s >>= 1) {
        if (t < s) red[t] = fmaxf(red[t], red[t + s]);
        __syncthreads();
    }
    m = red[0]; __syncthreads();

    float sum = 0.f;
#pragma unroll
    for (int i = 0; i < 16; i++) {
        vals[i] = __expf(vals[i] - m);
        sum += vals[i];
    }
    red[t] = sum; __syncthreads();
    for (int s = 128; s > 0; s >>= 1) {
        if (t < s) red[t] += red[t + s];
        __syncthreads();
    }
    float inv = 1.f / red[0];
#pragma unroll
    for (int i = 0; i < 16; i++) p[t + 256 * i] = vals[i] * inv;
}

// ============ K4: lambda_c[b,k,v] = sum_n kf[b,k,n]*v[b,v,n] ============
// vs padded to 129 floats/row: conflict-free column reads (was 32-way).
__global__ void __launch_bounds__(256) lambdac_kernel()
{
    __shared__ float kfs[16][128];
    __shared__ float vs[64][129];
    int b = blockIdx.y;
    int n0 = blockIdx.x * 128;
    int t = threadIdx.x;

    for (int i = t; i < 16 * 128; i += 256) {
        int k = i >> 7, n = i & 127;
        kfs[k][n] = g_kf[((size_t)b * 16 + k) * NN + n0 + n];
    }
    for (int i = t; i < 64 * 128; i += 256) {
        int v = i >> 7, n = i & 127;
        vs[v][n] = g_v[((size_t)b * 64 + v) * NN + n0 + n];
    }
    __syncthreads();

#pragma unroll
    for (int pq = 0; pq < 4; pq++) {
        int pid = t + 256 * pq;           // 0..1023
        int k = pid >> 6, v = pid & 63;
        float a = 0.f;
#pragma unroll 8
        for (int nn = 0; nn < 128; nn++) a += kfs[k][nn] * vs[v][nn];
        atomicAdd(&g_lc[(size_t)b * 1024 + pid], a);
    }
}

// ============ K5: fused positional lambda + output (v4 scalar, proven) ========
// out[b, h*64+v, (r,c)] = sum_k q[h,k,(r,c)] * lc[k,v]
//                       + sum_{di,dj} s[h,(di,dj),(r,c)] * v[v, r+di-11, c+dj-11]
// where s[h,(di,dj),(r,c)] = sum_k q[h,k,(r,c)] * emb[k,di,dj]
#define FUSED_SMEM_BYTES 100416

__global__ void __launch_bounds__(256, 2) fused_kernel(const float* __restrict__ emb,
                                                       float* __restrict__ out)
{
    extern __shared__ float sm[];
    float* q_s   = sm;            // [64 ch][64 c]
    float* lc_s  = sm + 4096;     // [16][64]
    float* emb_t = sm + 5120;     // [529 p][16 k]  (transposed)
    float* s_s   = sm + 13584;    // [4h][23dj][64c]
    float* vr_s  = sm + 19472;    // [64v][88]

    const int r = blockIdx.x, b = blockIdx.y;
    const int t = threadIdx.x;
    const int w = t >> 5, l = t & 31;

    // apply mapping: warp covers 8 strips x 4 vgroups (1-wf sh broadcasts)
    const int strip  = (l & 7) | ((w & 1) << 3);
    const int vgroup = (l >> 3) | ((w >> 1) << 2);
    const int c0 = strip * 4, v0 = vgroup * 4;

    // s-compute mapping: hh constant per warp, 6 dj per thread
    const int hh  = w & 3;
    const int djb = ((w >> 2) * 12) + ((l >> 4) * 6);   // 0,6,12,18
    const int cq  = l & 15;

    // v-row fill mapping
    const int col = t & 63, vv0 = t >> 6;

    // ---- persistent tiles ----
    for (int i = t; i < 4096; i += 256) {
        int ch = i >> 6, c = i & 63;
        q_s[i] = g_q[((size_t)b * 64 + ch) * NN + r * WH + c];
    }
    for (int i = t; i < 1024; i += 256) lc_s[i] = g_lc[b * 1024 + i];
    for (int i = t; i < 8464; i += 256) {
        int p = i >> 4, k = i & 15;               // transpose on load
        emb_t[i] = emb[k * 529 + p];
    }
    for (int i = t; i < 5632; i += 256) vr_s[i] = 0.f;   // halo stays zero
    __syncthreads();

    // ---- init acc with content lambda ----
    float acc[4][4][4];
#pragma unroll
    for (int h = 0; h < 4; h++)
#pragma unroll
        for (int v = 0; v < 4; v++)
#pragma unroll
            for (int c = 0; c < 4; c++) acc[h][v][c] = 0.f;

    const float4* q4 = (const float4*)q_s;          // [64 ch][16] float4
#pragma unroll
    for (int k = 0; k < 16; k++) {
        float lv[4];
#pragma unroll
        for (int v = 0; v < 4; v++) lv[v] = lc_s[k * 64 + v0 + v];
#pragma unroll
        for (int h = 0; h < 4; h++) {
            float4 qv = q4[(h * 16 + k) * 16 + strip];
#pragma unroll
            for (int v = 0; v < 4; v++) {
                acc[h][v][0] += qv.x * lv[v]; acc[h][v][1] += qv.y * lv[v];
                acc[h][v][2] += qv.z * lv[v]; acc[h][v][3] += qv.w * lv[v];
            }
        }
    }

    const int di_lo = (r < PADK) ? (PADK - r) : 0;
    const int di_hi = (r > 52) ? (74 - r) : 22;
    const float* vbase = &g_v[(size_t)b * 64 * NN];
    float4* s4 = (float4*)s_s;                      // [4*23][16] float4

#pragma unroll 1
    for (int di = di_lo; di <= di_hi; di++) {
        const int rr = r + di - PADK;
        __syncthreads();   // A: previous apply done reading s_s / vr_s

        // prefetch v row (global, latency hidden behind s-compute)
        float vreg[16];
#pragma unroll
        for (int i = 0; i < 16; i++)
            vreg[i] = vbase[(size_t)(4 * i + vv0) * NN + rr * WH + col];

        // ---- s-compute: (hh, cq), dj in [djb, djb+5]; sv accumulators ----
        {
            float4 sv[6];
#pragma unroll
            for (int j = 0; j < 6; j++) sv[j] = make_float4(0.f, 0.f, 0.f, 0.f);

            const float* ebase = &emb_t[(di * MMK) * 16];
#pragma unroll
            for (int kc = 0; kc < 4; kc++) {
                float4 qr[4];
#pragma unroll
                for (int kk = 0; kk < 4; kk++)
                    qr[kk] = q4[(hh * 16 + kc * 4 + kk) * 16 + cq];
#pragma unroll
                for (int j = 0; j < 6; j++) {
                    const int dj = djb + j;
                    if (dj < MMK) {
                        float4 ew = *(const float4*)&ebase[dj * 16 + kc * 4];
                        sv[j].x += ew.x * qr[0].x + ew.y * qr[1].x
                                 + ew.z * qr[2].x + ew.w * qr[3].x;
                        sv[j].y += ew.x * qr[0].y + ew.y * qr[1].y
                                 + ew.z * qr[2].y + ew.w * qr[3].y;
                        sv[j].z += ew.x * qr[0].z + ew.y * qr[1].z
                                 + ew.z * qr[2].z + ew.w * qr[3].z;
                        sv[j].w += ew.x * qr[0].w + ew.y * qr[1].w
                                 + ew.z * qr[2].w + ew.w * qr[3].w;
                    }
                }
            }
#pragma unroll
            for (int j = 0; j < 6; j++) {
                const int dj = djb + j;
                if (dj < MMK) s4[(hh * 23 + dj) * 16 + cq] = sv[j];
            }
        }

        // store prefetched v row
#pragma unroll
        for (int i = 0; i < 16; i++)
            vr_s[(4 * i + vv0) * 88 + PADK + col] = vreg[i];
        __syncthreads();   // B: s_s and vr_s ready

        // ---- apply: sliding 8-float window per v channel ----
        float vw[4][8];
#pragma unroll
        for (int v = 0; v < 4; v++) {
            float4 a0 = *(const float4*)&vr_s[(v0 + v) * 88 + c0];
            float4 a1 = *(const float4*)&vr_s[(v0 + v) * 88 + c0 + 4];
            vw[v][0] = a0.x; vw[v][1] = a0.y; vw[v][2] = a0.z; vw[v][3] = a0.w;
            vw[v][4] = a1.x; vw[v][5] = a1.y; vw[v][6] = a1.z; vw[v][7] = a1.w;
        }

#pragma unroll
        for (int djq = 0; djq < 6; djq++) {
#pragma unroll
            for (int djl = 0; djl < 4; djl++) {
                const int dj = djq * 4 + djl;
                if (dj < MMK) {
                    float4 sh[4];
#pragma unroll
                    for (int h = 0; h < 4; h++)
                        sh[h] = s4[(h * 23 + dj) * 16 + strip];
#pragma unroll
                    for (int h = 0; h < 4; h++)
#pragma unroll
                        for (int v = 0; v < 4; v++) {
                            acc[h][v][0] += sh[h].x * vw[v][djl + 0];
                            acc[h][v][1] += sh[h].y * vw[v][djl + 1];
                            acc[h][v][2] += sh[h].z * vw[v][djl + 2];
                            acc[h][v][3] += sh[h].w * vw[v][djl + 3];
                        }
                }
            }
            if (djq < 5) {
#pragma unroll
                for (int v = 0; v < 4; v++) {
                    vw[v][0] = vw[v][4]; vw[v][1] = vw[v][5];
                    vw[v][2] = vw[v][6]; vw[v][3] = vw[v][7];
                    float4 nx = *(const float4*)&vr_s[(v0 + v) * 88 + c0 + (djq + 2) * 4];
                    vw[v][4] = nx.x; vw[v][5] = nx.y; vw[v][6] = nx.z; vw[v][7] = nx.w;
                }
            }
        }
    }

    // ---- output ----
#pragma unroll
    for (int h = 0; h < 4; h++)
#pragma unroll
        for (int v = 0; v < 4; v++) {
            float4 o4 = make_float4(acc[h][v][0], acc[h][v][1],
                                    acc[h][v][2], acc[h][v][3]);
            *(float4*)&out[((size_t)b * 256 + h * 64 + v0 + v) * NN + r * WH + c0] = o4;
        }
}

// ============ launcher ============
extern "C" void kernel_launch(void* const* d_in, const int* in_sizes, int n_in,
                              void* d_out, int out_size)
{
    const float* x   = (const float*)d_in[0];
    const float* Wq  = (const float*)d_in[1];
    const float* qg  = (const float*)d_in[2];
    const float* qb  = (const float*)d_in[3];
    const float* qm  = (const float*)d_in[4];
    const float* qv  = (const float*)d_in[5];
    const float* Wk  = (const float*)d_in[6];
    const float* Wv  = (const float*)d_in[7];
    const float* vg  = (const float*)d_in[8];
    const float* vb  = (const float*)d_in[9];
    const float* vm  = (const float*)d_in[10];
    const float* vvr = (const float*)d_in[11];
    const float* emb = (const float*)d_in[12];
    float* out = (float*)d_out;

    cudaFuncSetAttribute(fused_kernel,
                         cudaFuncAttributeMaxDynamicSharedMemorySize,
                         FUSED_SMEM_BYTES);

    fold_kernel<<<OCH, 256>>>(Wq, qg, qb, qm, qv, Wk, Wv, vg, vb, vm, vvr);
    zero_lc_kernel<<<(BB * 16 * 64 + 255) / 256, 256>>>();
    proj_kernel<<<dim3(32, BB), 256>>>(x);
    softmax_kernel<<<BB * 16, 256>>>();
    lambdac_kernel<<<dim3(32, BB), 256>>>();
    fused_kernel<<<dim3(WH, BB), 256, FUSED_SMEM_BYTES>>>(emb, out);
}